// round 3
// baseline (speedup 1.0000x reference)
#include <cuda_runtime.h>
#include <cuda_bf16.h>
#include <cstdint>

#define VOCAB  100000
#define EMBED  100
#define HIDDEN 128
#define NOISE  10
#define BATCH  2048
#define CIN    (EMBED + NOISE)   // 110

// ---------------- scratch (device globals; no allocations allowed) ----------
__device__ __nv_bfloat16 g_fcw[(size_t)VOCAB * HIDDEN];  // fc_w in bf16
__device__ __nv_bfloat16 g_h[BATCH * HIDDEN];            // LSTM output h in bf16
__device__ float g_WT[CIN * 512];                        // W_ih transposed [k][gate]
__device__ float g_bsum[512];                            // b_ih + b_hh
__device__ float g_rowsum[BATCH];                        // softmax denominators

// exp with cheap polynomial (logits are tiny); __expf fallback for safety
__device__ __forceinline__ float fexp(float x) {
    float r = fmaf(x, 1.388888889e-3f, 8.333333333e-3f);
    r = fmaf(r, x, 4.166666667e-2f);
    r = fmaf(r, x, 1.666666667e-1f);
    r = fmaf(r, x, 0.5f);
    r = fmaf(r, x, 1.0f);
    r = fmaf(r, x, 1.0f);
    if (fabsf(x) > 0.6f) r = __expf(x);
    return r;
}

// warp-level bf16 MMA: D(16x8,f32) += A(16x16) * B(16x8)
__device__ __forceinline__ void mma16816(float* c, const uint32_t* a, const uint32_t* b) {
    asm volatile(
        "mma.sync.aligned.m16n8k16.row.col.f32.bf16.bf16.f32 "
        "{%0,%1,%2,%3}, {%4,%5,%6,%7}, {%8,%9}, {%0,%1,%2,%3};"
        : "+f"(c[0]), "+f"(c[1]), "+f"(c[2]), "+f"(c[3])
        : "r"(a[0]), "r"(a[1]), "r"(a[2]), "r"(a[3]), "r"(b[0]), "r"(b[1]));
}

// ---------------- kernel 0a: fc_w fp32 -> bf16 ------------------------------
__global__ void convert_fcw_kernel(const float* __restrict__ fc_w) {
    size_t i = (size_t)blockIdx.x * blockDim.x + threadIdx.x;
    size_t n4 = (size_t)VOCAB * HIDDEN / 4;
    if (i < n4) {
        float4 v = reinterpret_cast<const float4*>(fc_w)[i];
        ushort4 u;
        u.x = __bfloat16_as_ushort(__float2bfloat16(v.x));
        u.y = __bfloat16_as_ushort(__float2bfloat16(v.y));
        u.z = __bfloat16_as_ushort(__float2bfloat16(v.z));
        u.w = __bfloat16_as_ushort(__float2bfloat16(v.w));
        reinterpret_cast<ushort4*>(g_fcw)[i] = u;
    }
}

// ---------------- kernel 0b: prep (bias sum, W_ih transpose, zero sums) -----
__global__ void prep_kernel(const float* __restrict__ W_ih,
                            const float* __restrict__ b_ih,
                            const float* __restrict__ b_hh) {
    int tid = threadIdx.x;
    if (tid < 512) g_bsum[tid] = b_ih[tid] + b_hh[tid];
    for (int i = tid; i < CIN * 512; i += blockDim.x) {
        int k = i >> 9, j = i & 511;
        g_WT[i] = W_ih[j * CIN + k];
    }
    for (int i = tid; i < BATCH; i += blockDim.x) g_rowsum[i] = 0.f;
}

// ---------------- kernel 1: embed + LSTM step -> h (bf16) -------------------
__global__ void __launch_bounds__(128) lstm_kernel(const int* __restrict__ x,
                                                   const float* __restrict__ noise,
                                                   const float* __restrict__ emb) {
    __shared__ float comb[8][112];
    int tid = threadIdx.x;
    int row0 = blockIdx.x * 8;
    for (int idx = tid; idx < 8 * CIN; idx += 128) {
        int b = idx / CIN, k = idx % CIN;
        int r = row0 + b;
        comb[b][k] = (k < EMBED) ? emb[(size_t)x[r] * EMBED + k]
                                 : noise[r * NOISE + (k - EMBED)];
    }
    __syncthreads();
    int j = tid;
    float bi = g_bsum[j], bg = g_bsum[256 + j], bo = g_bsum[384 + j];
    float acci[8], accg[8], acco[8];
#pragma unroll
    for (int b = 0; b < 8; b++) { acci[b] = bi; accg[b] = bg; acco[b] = bo; }
    for (int k = 0; k < CIN; k++) {
        float wi = g_WT[k * 512 + j];
        float wg = g_WT[k * 512 + 256 + j];
        float wo = g_WT[k * 512 + 384 + j];
#pragma unroll
        for (int b = 0; b < 8; b++) {
            float cv = comb[b][k];
            acci[b] = fmaf(wi, cv, acci[b]);
            accg[b] = fmaf(wg, cv, accg[b]);
            acco[b] = fmaf(wo, cv, acco[b]);
        }
    }
#pragma unroll
    for (int b = 0; b < 8; b++) {
        float ig = 1.f / (1.f + __expf(-acci[b]));
        float gg = tanhf(accg[b]);
        float cc = ig * gg;
        float og = 1.f / (1.f + __expf(-acco[b]));
        float hh = og * tanhf(cc);
        g_h[(row0 + b) * HIDDEN + j] = __float2bfloat16(hh);
    }
}

// ---------------- GEMM + softmax (mma.sync bf16, M-loop per CTA) ------------
// Per CTA: 128-col vocab tile, 256 threads (8 warps: 4 along M x 2 along N).
// Warp tile: 32(M) x 64(N). B staged once in smem; loop 16 M-tiles of h.
// Pass1 (!WRITE): per-row sum of exp(logit+bias) -> atomicAdd.
// Pass2 (WRITE): exp*inv_sum -> padded smem bounce -> coalesced fp32 stores.

// smem layout (bytes). Row stride 272B (136 bf16): bank-conflict-free frags.
#define OFF_FCB  0
#define OFF_A    1024
#define OFF_B    (1024 + 34816)      // 35840
#define GEMM_SMEM (1024 + 34816 * 2) // 70656; epi buffer reuses OFF_A region
#define ASTRIDE  272                 // bytes per row (128 bf16 + 8 pad)

template <bool WRITE>
__global__ void __launch_bounds__(256) gemm_softmax(const float* __restrict__ fc_b,
                                                    float* __restrict__ out) {
    extern __shared__ char smem[];
    const int tid = threadIdx.x;
    const int wid = tid >> 5, lane = tid & 31;
    const int warp_m = wid & 3, warp_n = wid >> 2;   // 4 x 2 warp grid
    const int r4 = lane >> 2, kq = (lane & 3) << 1;  // fragment lane coords
    const int jbase = blockIdx.x * 128;
    const int ncols = min(128, VOCAB - jbase);
    float* fcb = reinterpret_cast<float*>(smem + OFF_FCB);

    { // bias tile
        if (tid < 128) {
            int v = jbase + tid;
            fcb[tid] = (v < VOCAB) ? fc_b[v] : 0.f;
        }
    }
    // B tile: fc_w_bf16 rows [jbase, jbase+128), zero-padded rows beyond vocab
    for (int i = tid; i < 2048; i += 256) {
        int n = i >> 4, q = i & 15;
        uint4 val = make_uint4(0, 0, 0, 0);
        int v = jbase + n;
        if (v < VOCAB)
            val = *reinterpret_cast<const uint4*>(
                reinterpret_cast<const char*>(g_fcw) + ((size_t)v * 256 + q * 16));
        *reinterpret_cast<uint4*>(smem + OFF_B + n * ASTRIDE + q * 16) = val;
    }

    const int m_base = warp_m * 32;

    for (int m = 0; m < 16; m++) {
        __syncthreads();   // B ready (m==0) / epi-store of prev iter done
        // A tile: h rows [m*128, m*128+128)
        for (int i = tid; i < 2048; i += 256) {
            int r = i >> 4, q = i & 15;
            *reinterpret_cast<uint4*>(smem + OFF_A + r * ASTRIDE + q * 16) =
                *reinterpret_cast<const uint4*>(
                    reinterpret_cast<const char*>(g_h) + ((size_t)(m * 128 + r) * 256 + q * 16));
        }
        __syncthreads();

        float acc[2][8][4];
#pragma unroll
        for (int mb = 0; mb < 2; mb++)
#pragma unroll
            for (int nb = 0; nb < 8; nb++)
#pragma unroll
                for (int j = 0; j < 4; j++) acc[mb][nb][j] = 0.f;

#pragma unroll
        for (int kc = 0; kc < 8; kc++) {
            const int k0 = kc * 16 + kq;
            uint32_t afrag[2][4];
#pragma unroll
            for (int mb = 0; mb < 2; mb++) {
                const char* ar = smem + OFF_A + (m_base + mb * 16 + r4) * ASTRIDE;
                afrag[mb][0] = *reinterpret_cast<const uint32_t*>(ar + k0 * 2);
                afrag[mb][1] = *reinterpret_cast<const uint32_t*>(ar + 8 * ASTRIDE + k0 * 2);
                afrag[mb][2] = *reinterpret_cast<const uint32_t*>(ar + (k0 + 8) * 2);
                afrag[mb][3] = *reinterpret_cast<const uint32_t*>(ar + 8 * ASTRIDE + (k0 + 8) * 2);
            }
#pragma unroll
            for (int nb = 0; nb < 8; nb++) {
                const char* br = smem + OFF_B + (warp_n * 64 + nb * 8 + r4) * ASTRIDE;
                uint32_t bfrag[2];
                bfrag[0] = *reinterpret_cast<const uint32_t*>(br + k0 * 2);
                bfrag[1] = *reinterpret_cast<const uint32_t*>(br + (k0 + 8) * 2);
                mma16816(acc[0][nb], afrag[0], bfrag);
                mma16816(acc[1][nb], afrag[1], bfrag);
            }
        }

        if (!WRITE) {
            // Per-lane partial sum of exp over owned cols, quad-reduce, atomic.
#pragma unroll
            for (int mb = 0; mb < 2; mb++) {
#pragma unroll
                for (int p = 0; p < 2; p++) {
                    const int rloc = m_base + mb * 16 + p * 8 + r4;
                    float s = 0.f;
#pragma unroll
                    for (int nb = 0; nb < 8; nb++) {
#pragma unroll
                        for (int j = 0; j < 2; j++) {
                            int ct = warp_n * 64 + nb * 8 + kq + j;
                            float l = acc[mb][nb][p * 2 + j] + fcb[ct];
                            if (ct < ncols) s += fexp(l);
                        }
                    }
                    s += __shfl_xor_sync(0xffffffffu, s, 1);
                    s += __shfl_xor_sync(0xffffffffu, s, 2);
                    if ((lane & 3) == 0)
                        atomicAdd(&g_rowsum[m * 128 + rloc], s);
                }
            }
        } else {
            float* epi = reinterpret_cast<float*>(smem + OFF_A);  // reuse A region
            // two 64-col halves; half h written by warps with warp_n == h
#pragma unroll
            for (int h = 0; h < 2; h++) {
                __syncthreads();   // A-frag reads (h==0) / prev-half stores done
                if (warp_n == h) {
#pragma unroll
                    for (int mb = 0; mb < 2; mb++) {
#pragma unroll
                        for (int p = 0; p < 2; p++) {
                            const int rloc = m_base + mb * 16 + p * 8 + r4;
                            const float invs = 1.0f / g_rowsum[m * 128 + rloc];
#pragma unroll
                            for (int nb = 0; nb < 8; nb++) {
#pragma unroll
                                for (int j = 0; j < 2; j++) {
                                    int cl = nb * 8 + kq + j;     // col within half
                                    float l = acc[mb][nb][p * 2 + j] + fcb[h * 64 + cl];
                                    epi[rloc * 68 + cl] = fexp(l) * invs;
                                }
                            }
                        }
                    }
                }
                __syncthreads();
                // coalesced store: 128 rows x 64 cols fp32
                for (int i = tid; i < 2048; i += 256) {
                    int r = i >> 4, q = i & 15;
                    if (h * 64 + q * 4 + 4 <= ncols) {
                        uint4 v = *reinterpret_cast<const uint4*>(
                            reinterpret_cast<const char*>(epi) + r * 68 * 4 + q * 16);
                        *reinterpret_cast<uint4*>(
                            &out[(size_t)(m * 128 + r) * VOCAB + jbase + h * 64 + q * 4]) = v;
                    }
                }
            }
        }
    }
}

// ---------------- launch ----------------------------------------------------
extern "C" void kernel_launch(void* const* d_in, const int* in_sizes, int n_in,
                              void* d_out, int out_size) {
    const int*   x      = (const int*)d_in[0];
    const float* noise  = (const float*)d_in[1];
    const float* emb    = (const float*)d_in[2];
    const float* W_ih   = (const float*)d_in[3];
    // d_in[4] = W_hh unused (h0 == 0)
    const float* b_ih   = (const float*)d_in[5];
    const float* b_hh   = (const float*)d_in[6];
    const float* fc_w   = (const float*)d_in[7];
    const float* fc_b   = (const float*)d_in[8];
    float* out = (float*)d_out;

    static bool attr_set = false;
    if (!attr_set) {
        cudaFuncSetAttribute(gemm_softmax<false>, cudaFuncAttributeMaxDynamicSharedMemorySize, GEMM_SMEM);
        cudaFuncSetAttribute(gemm_softmax<true>,  cudaFuncAttributeMaxDynamicSharedMemorySize, GEMM_SMEM);
        attr_set = true;
    }

    int n4 = VOCAB * HIDDEN / 4;
    convert_fcw_kernel<<<(n4 + 255) / 256, 256>>>(fc_w);
    prep_kernel<<<1, 512>>>(W_ih, b_ih, b_hh);
    lstm_kernel<<<BATCH / 8, 128>>>(x, noise, emb);

    int ntiles = (VOCAB + 127) / 128;  // 782
    gemm_softmax<false><<<ntiles, 256, GEMM_SMEM>>>(fc_b, nullptr);
    gemm_softmax<true><<<ntiles, 256, GEMM_SMEM>>>(fc_b, out);
}

// round 4
// speedup vs baseline: 1.5997x; 1.5997x over previous
#include <cuda_runtime.h>
#include <cuda_bf16.h>
#include <cuda_fp16.h>
#include <cstdint>

#define VOCAB  100000
#define EMBED  100
#define HIDDEN 128
#define NOISE  10
#define BATCH  2048
#define CIN    (EMBED + NOISE)   // 110

// ---------------- scratch (device globals; no allocations allowed) ----------
__device__ __nv_bfloat16 g_fcw[(size_t)VOCAB * HIDDEN];  // fc_w in bf16
__device__ __nv_bfloat16 g_h[BATCH * HIDDEN];            // LSTM output h in bf16
__device__ float g_WT[CIN * 512];                        // W_ih transposed [k][gate]
__device__ float g_bsum[512];                            // b_ih + b_hh
__device__ float g_rowsum[BATCH];                        // softmax denominators
__device__ __half g_scrl[(size_t)BATCH * VOCAB];         // fp16 logits (410 MB)

// exp with cheap polynomial (logits are tiny); __expf fallback for safety
__device__ __forceinline__ float fexp(float x) {
    float r = fmaf(x, 1.388888889e-3f, 8.333333333e-3f);
    r = fmaf(r, x, 4.166666667e-2f);
    r = fmaf(r, x, 1.666666667e-1f);
    r = fmaf(r, x, 0.5f);
    r = fmaf(r, x, 1.0f);
    r = fmaf(r, x, 1.0f);
    if (fabsf(x) > 0.6f) r = __expf(x);
    return r;
}

__device__ __forceinline__ uint32_t smem_to_u32(const void* p) {
    uint32_t a;
    asm("{ .reg .u64 t; cvta.to.shared.u64 t, %1; cvt.u32.u64 %0, t; }" : "=r"(a) : "l"(p));
    return a;
}

// warp-level bf16 MMA: D(16x8,f32) += A(16x16) * B(16x8)
__device__ __forceinline__ void mma16816(float* c, const uint32_t* a, const uint32_t* b) {
    asm volatile(
        "mma.sync.aligned.m16n8k16.row.col.f32.bf16.bf16.f32 "
        "{%0,%1,%2,%3}, {%4,%5,%6,%7}, {%8,%9}, {%0,%1,%2,%3};"
        : "+f"(c[0]), "+f"(c[1]), "+f"(c[2]), "+f"(c[3])
        : "r"(a[0]), "r"(a[1]), "r"(a[2]), "r"(a[3]), "r"(b[0]), "r"(b[1]));
}

__device__ __forceinline__ void ldsm4(uint32_t* r, uint32_t addr) {
    asm volatile("ldmatrix.sync.aligned.m8n8.x4.shared.b16 {%0,%1,%2,%3}, [%4];"
                 : "=r"(r[0]), "=r"(r[1]), "=r"(r[2]), "=r"(r[3]) : "r"(addr));
}

// ---------------- kernel 0a: fc_w fp32 -> bf16 ------------------------------
__global__ void convert_fcw_kernel(const float* __restrict__ fc_w) {
    size_t i = (size_t)blockIdx.x * blockDim.x + threadIdx.x;
    size_t n4 = (size_t)VOCAB * HIDDEN / 4;
    if (i < n4) {
        float4 v = reinterpret_cast<const float4*>(fc_w)[i];
        ushort4 u;
        u.x = __bfloat16_as_ushort(__float2bfloat16(v.x));
        u.y = __bfloat16_as_ushort(__float2bfloat16(v.y));
        u.z = __bfloat16_as_ushort(__float2bfloat16(v.z));
        u.w = __bfloat16_as_ushort(__float2bfloat16(v.w));
        reinterpret_cast<ushort4*>(g_fcw)[i] = u;
    }
}

// ---------------- kernel 0b: prep (bias sum, W_ih transpose, zero sums) -----
__global__ void prep_kernel(const float* __restrict__ W_ih,
                            const float* __restrict__ b_ih,
                            const float* __restrict__ b_hh) {
    int tid = threadIdx.x;
    if (tid < 512) g_bsum[tid] = b_ih[tid] + b_hh[tid];
    for (int i = tid; i < CIN * 512; i += blockDim.x) {
        int k = i >> 9, j = i & 511;
        g_WT[i] = W_ih[j * CIN + k];
    }
    for (int i = tid; i < BATCH; i += blockDim.x) g_rowsum[i] = 0.f;
}

// ---------------- kernel 1: embed + LSTM step -> h (bf16) -------------------
__global__ void __launch_bounds__(128) lstm_kernel(const int* __restrict__ x,
                                                   const float* __restrict__ noise,
                                                   const float* __restrict__ emb) {
    __shared__ float comb[8][112];
    int tid = threadIdx.x;
    int row0 = blockIdx.x * 8;
    for (int idx = tid; idx < 8 * CIN; idx += 128) {
        int b = idx / CIN, k = idx % CIN;
        int r = row0 + b;
        comb[b][k] = (k < EMBED) ? emb[(size_t)x[r] * EMBED + k]
                                 : noise[r * NOISE + (k - EMBED)];
    }
    __syncthreads();
    int j = tid;
    float bi = g_bsum[j], bg = g_bsum[256 + j], bo = g_bsum[384 + j];
    float acci[8], accg[8], acco[8];
#pragma unroll
    for (int b = 0; b < 8; b++) { acci[b] = bi; accg[b] = bg; acco[b] = bo; }
    for (int k = 0; k < CIN; k++) {
        float wi = g_WT[k * 512 + j];
        float wg = g_WT[k * 512 + 256 + j];
        float wo = g_WT[k * 512 + 384 + j];
#pragma unroll
        for (int b = 0; b < 8; b++) {
            float cv = comb[b][k];
            acci[b] = fmaf(wi, cv, acci[b]);
            accg[b] = fmaf(wg, cv, accg[b]);
            acco[b] = fmaf(wo, cv, acco[b]);
        }
    }
#pragma unroll
    for (int b = 0; b < 8; b++) {
        float ig = 1.f / (1.f + __expf(-acci[b]));
        float gg = tanhf(accg[b]);
        float cc = ig * gg;
        float og = 1.f / (1.f + __expf(-acco[b]));
        float hh = og * tanhf(cc);
        g_h[(row0 + b) * HIDDEN + j] = __float2bfloat16(hh);
    }
}

// ---------------- GEMM + exp-sum + fp16-logit store (single pass) -----------
// Per CTA: 128-col vocab tile, 256 threads (8 warps: 4 along M x 2 along N).
// Warp tile 32(M) x 64(N); ldmatrix.x4 fragment feeds. For each of 16 M-tiles:
// MMA -> logits; rowsum atomics; biased logits -> padded smem -> coalesced
// fp16 store into g_scrl.
#define OFF_FCB  0
#define OFF_A    1024
#define OFF_B    (1024 + 34816)      // 35840
#define GEMM_SMEM (1024 + 34816 * 2) // 70656; epi buffer reuses OFF_A region
#define ASTRIDE  272                 // bytes per row (128 bf16 + 8 pad)

__global__ void __launch_bounds__(256) gemm_pass(const float* __restrict__ fc_b) {
    extern __shared__ char smem[];
    const uint32_t sa = smem_to_u32(smem);
    const int tid = threadIdx.x;
    const int wid = tid >> 5, lane = tid & 31;
    const int warp_m = wid & 3, warp_n = wid >> 2;   // 4 x 2 warp grid
    const int r4 = lane >> 2, kq = (lane & 3) << 1;  // fragment lane coords
    const int jbase = blockIdx.x * 128;
    const int ncols = min(128, VOCAB - jbase);
    float* fcb = reinterpret_cast<float*>(smem + OFF_FCB);
    __half2* epi2 = reinterpret_cast<__half2*>(smem + OFF_A);  // reuse A region

    if (tid < 128) {
        int v = jbase + tid;
        fcb[tid] = (v < VOCAB) ? fc_b[v] : 0.f;
    }
    // B tile: fc_w_bf16 rows [jbase, jbase+128), zero-padded rows beyond vocab
    for (int i = tid; i < 2048; i += 256) {
        int n = i >> 4, q = i & 15;
        uint4 val = make_uint4(0, 0, 0, 0);
        int v = jbase + n;
        if (v < VOCAB)
            val = *reinterpret_cast<const uint4*>(
                reinterpret_cast<const char*>(g_fcw) + ((size_t)v * 256 + q * 16));
        *reinterpret_cast<uint4*>(smem + OFF_B + n * ASTRIDE + q * 16) = val;
    }

    const int m_base = warp_m * 32;

    // loop-invariant ldmatrix base addresses (per-lane)
    // A x4: lane l -> row (l&15), k-halfsel (l>>4)*8
    uint32_t baseA[2], baseB[4];
#pragma unroll
    for (int mb = 0; mb < 2; mb++)
        baseA[mb] = sa + OFF_A + (m_base + mb * 16 + (lane & 15)) * ASTRIDE
                  + (((lane >> 4) & 1) << 3) * 2;
    // B x4 (2 n-blocks of 8): groups of 8 lanes ->
    //   g0:(n+0,k0) g1:(n+0,k0+8) g2:(n+8,k0) g3:(n+8,k0+8)
#pragma unroll
    for (int nbp = 0; nbp < 4; nbp++)
        baseB[nbp] = sa + OFF_B
                   + (warp_n * 64 + nbp * 16 + (((lane >> 4) & 1) << 3) + (lane & 7)) * ASTRIDE
                   + (((lane >> 3) & 1) << 3) * 2;

    for (int m = 0; m < 16; m++) {
        __syncthreads();   // prev-iter epi copy done -> A region writable
        // A tile: h rows [m*128, m*128+128)
        for (int i = tid; i < 2048; i += 256) {
            int r = i >> 4, q = i & 15;
            *reinterpret_cast<uint4*>(smem + OFF_A + r * ASTRIDE + q * 16) =
                *reinterpret_cast<const uint4*>(
                    reinterpret_cast<const char*>(g_h) + ((size_t)(m * 128 + r) * 256 + q * 16));
        }
        __syncthreads();

        float acc[2][8][4];
#pragma unroll
        for (int mb = 0; mb < 2; mb++)
#pragma unroll
            for (int nb = 0; nb < 8; nb++)
#pragma unroll
                for (int j = 0; j < 4; j++) acc[mb][nb][j] = 0.f;

#pragma unroll
        for (int kc = 0; kc < 8; kc++) {
            const uint32_t koff = kc * 32;   // 16 k * 2 bytes
            uint32_t a0[4], a1[4];
            ldsm4(a0, baseA[0] + koff);
            ldsm4(a1, baseA[1] + koff);
#pragma unroll
            for (int nbp = 0; nbp < 4; nbp++) {
                uint32_t bb[4];
                ldsm4(bb, baseB[nbp] + koff);
                mma16816(acc[0][2 * nbp + 0], a0, &bb[0]);
                mma16816(acc[1][2 * nbp + 0], a1, &bb[0]);
                mma16816(acc[0][2 * nbp + 1], a0, &bb[2]);
                mma16816(acc[1][2 * nbp + 1], a1, &bb[2]);
            }
        }

        __syncthreads();   // all A-frag reads done -> epi region writable

        // epilogue: bias, exp-sum (atomics), fp16 logit -> padded smem
#pragma unroll
        for (int mb = 0; mb < 2; mb++) {
#pragma unroll
            for (int p = 0; p < 2; p++) {
                const int rloc = m_base + mb * 16 + p * 8 + r4;
                float s = 0.f;
#pragma unroll
                for (int nb = 0; nb < 8; nb++) {
                    int col = warp_n * 64 + nb * 8 + kq;
                    float l0 = acc[mb][nb][p * 2 + 0] + fcb[col];
                    float l1 = acc[mb][nb][p * 2 + 1] + fcb[col + 1];
                    if (col < ncols) s += fexp(l0) + fexp(l1);
                    epi2[rloc * 68 + (col >> 1)] = __floats2half2_rn(l0, l1);
                }
                s += __shfl_xor_sync(0xffffffffu, s, 1);
                s += __shfl_xor_sync(0xffffffffu, s, 2);
                if ((lane & 3) == 0)
                    atomicAdd(&g_rowsum[m * 128 + rloc], s);
            }
        }
        __syncthreads();

        // coalesced fp16 store: 128 rows x 128 halves (256B/row)
        for (int i = tid; i < 2048; i += 256) {
            int r = i >> 4, q = i & 15;
            if (q * 8 + 8 <= ncols) {
                uint4 v = *reinterpret_cast<const uint4*>(smem + OFF_A + r * ASTRIDE + q * 16);
                __stcs(reinterpret_cast<uint4*>(
                           g_scrl + (size_t)(m * 128 + r) * VOCAB + jbase + q * 8), v);
            }
        }
    }
}

// ---------------- pass 2: scale (memory-bound) -------------------------------
// out[row, col] = exp(logit_fp16) / rowsum[row]; 8 elems per thread.
__global__ void __launch_bounds__(256) scale_kernel(float* __restrict__ out) {
    const uint32_t nq_row = VOCAB / 8;                 // 12500
    uint32_t t = blockIdx.x * 256 + threadIdx.x;
    if (t >= (uint32_t)BATCH * nq_row) return;
    uint32_t row = t / nq_row;
    uint32_t cq = t - row * nq_row;
    float invs = 1.0f / g_rowsum[row];
    const uint4* src = reinterpret_cast<const uint4*>(g_scrl + (size_t)row * VOCAB) + cq;
    uint4 v = __ldcs(src);
    float4 o0, o1;
    {
        __half2 h;
        h = *reinterpret_cast<__half2*>(&v.x);
        o0.x = fexp(__low2float(h)) * invs;  o0.y = fexp(__high2float(h)) * invs;
        h = *reinterpret_cast<__half2*>(&v.y);
        o0.z = fexp(__low2float(h)) * invs;  o0.w = fexp(__high2float(h)) * invs;
        h = *reinterpret_cast<__half2*>(&v.z);
        o1.x = fexp(__low2float(h)) * invs;  o1.y = fexp(__high2float(h)) * invs;
        h = *reinterpret_cast<__half2*>(&v.w);
        o1.z = fexp(__low2float(h)) * invs;  o1.w = fexp(__high2float(h)) * invs;
    }
    float4* dst = reinterpret_cast<float4*>(out + (size_t)row * VOCAB) + cq * 2;
    __stcs(dst, o0);
    __stcs(dst + 1, o1);
}

// ---------------- launch ----------------------------------------------------
extern "C" void kernel_launch(void* const* d_in, const int* in_sizes, int n_in,
                              void* d_out, int out_size) {
    const int*   x      = (const int*)d_in[0];
    const float* noise  = (const float*)d_in[1];
    const float* emb    = (const float*)d_in[2];
    const float* W_ih   = (const float*)d_in[3];
    // d_in[4] = W_hh unused (h0 == 0)
    const float* b_ih   = (const float*)d_in[5];
    const float* b_hh   = (const float*)d_in[6];
    const float* fc_w   = (const float*)d_in[7];
    const float* fc_b   = (const float*)d_in[8];
    float* out = (float*)d_out;

    cudaFuncSetAttribute(gemm_pass, cudaFuncAttributeMaxDynamicSharedMemorySize, GEMM_SMEM);

    int n4 = VOCAB * HIDDEN / 4;
    convert_fcw_kernel<<<(n4 + 255) / 256, 256>>>(fc_w);
    prep_kernel<<<1, 512>>>(W_ih, b_ih, b_hh);
    lstm_kernel<<<BATCH / 8, 128>>>(x, noise, emb);

    int ntiles = (VOCAB + 127) / 128;  // 782
    gemm_pass<<<ntiles, 256, GEMM_SMEM>>>(fc_b);

    uint32_t nthr = (uint32_t)BATCH * (VOCAB / 8);   // 25.6M
    scale_kernel<<<(nthr + 255) / 256, 256>>>(out);
}

// round 6
// speedup vs baseline: 1.8161x; 1.1353x over previous
#include <cuda_runtime.h>
#include <cuda_bf16.h>
#include <cuda_fp16.h>
#include <cstdint>

#define VOCAB  100000
#define EMBED  100
#define HIDDEN 128
#define NOISE  10
#define BATCH  2048
#define CIN    (EMBED + NOISE)   // 110

// ---------------- scratch (device globals; no allocations allowed) ----------
__device__ __nv_bfloat16 g_fcw[(size_t)VOCAB * HIDDEN];  // fc_w in bf16
__device__ __nv_bfloat16 g_h[BATCH * HIDDEN];            // LSTM output h in bf16
__device__ float g_WT[CIN * 512];                        // W_ih transposed [k][gate]
__device__ float g_bsum[512];                            // b_ih + b_hh
__device__ float g_rowsum[BATCH];                        // softmax denominators
__device__ __half g_scrl[(size_t)BATCH * VOCAB];         // fp16 raw logits (410 MB)

__device__ __forceinline__ uint32_t smem_to_u32(const void* p) {
    uint32_t a;
    asm("{ .reg .u64 t; cvta.to.shared.u64 t, %1; cvt.u32.u64 %0, t; }" : "=r"(a) : "l"(p));
    return a;
}

// warp-level bf16 MMA: D(16x8,f32) += A(16x16) * B(16x8)
__device__ __forceinline__ void mma16816(float* c, const uint32_t* a, const uint32_t* b) {
    asm volatile(
        "mma.sync.aligned.m16n8k16.row.col.f32.bf16.bf16.f32 "
        "{%0,%1,%2,%3}, {%4,%5,%6,%7}, {%8,%9}, {%0,%1,%2,%3};"
        : "+f"(c[0]), "+f"(c[1]), "+f"(c[2]), "+f"(c[3])
        : "r"(a[0]), "r"(a[1]), "r"(a[2]), "r"(a[3]), "r"(b[0]), "r"(b[1]));
}

__device__ __forceinline__ void ldsm4(uint32_t* r, uint32_t addr) {
    asm volatile("ldmatrix.sync.aligned.m8n8.x4.shared.b16 {%0,%1,%2,%3}, [%4];"
                 : "=r"(r[0]), "=r"(r[1]), "=r"(r[2]), "=r"(r[3]) : "r"(addr));
}

__device__ __forceinline__ void cp_async16(uint32_t saddr, const void* gaddr) {
    asm volatile("cp.async.cg.shared.global [%0], [%1], 16;" :: "r"(saddr), "l"(gaddr));
}
__device__ __forceinline__ void cp_async_commit_wait() {
    asm volatile("cp.async.commit_group;");
    asm volatile("cp.async.wait_group 0;");
}

// ---------------- kernel 0a: fc_w fp32 -> bf16 ------------------------------
__global__ void convert_fcw_kernel(const float* __restrict__ fc_w) {
    size_t i = (size_t)blockIdx.x * blockDim.x + threadIdx.x;
    size_t n4 = (size_t)VOCAB * HIDDEN / 4;
    if (i < n4) {
        float4 v = reinterpret_cast<const float4*>(fc_w)[i];
        ushort4 u;
        u.x = __bfloat16_as_ushort(__float2bfloat16(v.x));
        u.y = __bfloat16_as_ushort(__float2bfloat16(v.y));
        u.z = __bfloat16_as_ushort(__float2bfloat16(v.z));
        u.w = __bfloat16_as_ushort(__float2bfloat16(v.w));
        reinterpret_cast<ushort4*>(g_fcw)[i] = u;
    }
}

// ---------------- kernel 0b: prep (bias sum, W_ih transpose, zero sums) -----
__global__ void prep_kernel(const float* __restrict__ W_ih,
                            const float* __restrict__ b_ih,
                            const float* __restrict__ b_hh) {
    int tid = threadIdx.x;
    if (tid < 512) g_bsum[tid] = b_ih[tid] + b_hh[tid];
    for (int i = tid; i < CIN * 512; i += blockDim.x) {
        int k = i >> 9, j = i & 511;
        g_WT[i] = W_ih[j * CIN + k];
    }
    for (int i = tid; i < BATCH; i += blockDim.x) g_rowsum[i] = 0.f;
}

// ---------------- kernel 1: embed + LSTM step -> h (bf16) -------------------
__global__ void __launch_bounds__(128) lstm_kernel(const int* __restrict__ x,
                                                   const float* __restrict__ noise,
                                                   const float* __restrict__ emb) {
    __shared__ float comb[8][112];
    int tid = threadIdx.x;
    int row0 = blockIdx.x * 8;
    for (int idx = tid; idx < 8 * CIN; idx += 128) {
        int b = idx / CIN, k = idx % CIN;
        int r = row0 + b;
        comb[b][k] = (k < EMBED) ? emb[(size_t)x[r] * EMBED + k]
                                 : noise[r * NOISE + (k - EMBED)];
    }
    __syncthreads();
    int j = tid;
    float bi = g_bsum[j], bg = g_bsum[256 + j], bo = g_bsum[384 + j];
    float acci[8], accg[8], acco[8];
#pragma unroll
    for (int b = 0; b < 8; b++) { acci[b] = bi; accg[b] = bg; acco[b] = bo; }
    for (int k = 0; k < CIN; k++) {
        float wi = g_WT[k * 512 + j];
        float wg = g_WT[k * 512 + 256 + j];
        float wo = g_WT[k * 512 + 384 + j];
#pragma unroll
        for (int b = 0; b < 8; b++) {
            float cv = comb[b][k];
            acci[b] = fmaf(wi, cv, acci[b]);
            accg[b] = fmaf(wg, cv, accg[b]);
            acco[b] = fmaf(wo, cv, acco[b]);
        }
    }
#pragma unroll
    for (int b = 0; b < 8; b++) {
        float ig = 1.f / (1.f + __expf(-acci[b]));
        float gg = tanhf(accg[b]);
        float cc = ig * gg;
        float og = 1.f / (1.f + __expf(-acco[b]));
        float hh = og * tanhf(cc);
        g_h[(row0 + b) * HIDDEN + j] = __float2bfloat16(hh);
    }
}

// ---------------- GEMM -> raw fp16 logits (single pass, lean epilogue) ------
// Per CTA: 128-col vocab tile, 256 threads (8 warps: 4 along M x 2 along N).
// Warp tile 32(M) x 64(N); ldmatrix.x4 feeds. Epilogue: pack half2 -> padded
// smem bounce -> coalesced fp16 stores. No bias / no exp / no atomics here.
#define OFF_A    0
#define OFF_B    34816
#define GEMM_SMEM (34816 * 2)        // 69632; epi buffer reuses OFF_A region
#define ASTRIDE  272                 // bytes per row (128 bf16 + 8 pad)

__global__ void __launch_bounds__(256) gemm_pass() {
    extern __shared__ char smem[];
    const uint32_t sa = smem_to_u32(smem);
    const int tid = threadIdx.x;
    const int wid = tid >> 5, lane = tid & 31;
    const int warp_m = wid & 3, warp_n = wid >> 2;   // 4 x 2 warp grid
    const int r4 = lane >> 2, kq = (lane & 3) << 1;  // fragment lane coords
    const int jbase = blockIdx.x * 128;
    const int ncols = min(128, VOCAB - jbase);
    __half2* epi2 = reinterpret_cast<__half2*>(smem + OFF_A);  // reuse A region

    // B tile: fc_w_bf16 rows [jbase, jbase+128), zero-padded rows beyond vocab
    for (int i = tid; i < 2048; i += 256) {
        int n = i >> 4, q = i & 15;
        int v = jbase + n;
        uint32_t dst = sa + OFF_B + n * ASTRIDE + q * 16;
        if (v < VOCAB) {
            cp_async16(dst, reinterpret_cast<const char*>(g_fcw) + ((size_t)v * 256 + q * 16));
        } else {
            *reinterpret_cast<uint4*>(smem + OFF_B + n * ASTRIDE + q * 16) = make_uint4(0, 0, 0, 0);
        }
    }
    cp_async_commit_wait();

    const int m_base = warp_m * 32;

    // loop-invariant ldmatrix base addresses (per-lane)
    uint32_t baseA[2], baseB[4];
#pragma unroll
    for (int mb = 0; mb < 2; mb++)
        baseA[mb] = sa + OFF_A + (m_base + mb * 16 + (lane & 15)) * ASTRIDE
                  + (((lane >> 4) & 1) << 3) * 2;
#pragma unroll
    for (int nbp = 0; nbp < 4; nbp++)
        baseB[nbp] = sa + OFF_B
                   + (warp_n * 64 + nbp * 16 + (((lane >> 4) & 1) << 3) + (lane & 7)) * ASTRIDE
                   + (((lane >> 3) & 1) << 3) * 2;

    // per-thread A-load / bounce indices
    const int lr = tid >> 4, lq = tid & 15;   // 16 rows x 16 quads per pass of 256

    for (int m = 0; m < 16; m++) {
        __syncthreads();   // prev-iter bounce reads done -> A region writable
        // A tile: h rows [m*128, m*128+128) via cp.async (8 x 16B per thread)
#pragma unroll
        for (int s = 0; s < 8; s++) {
            int r = lr + s * 16;
            cp_async16(sa + OFF_A + r * ASTRIDE + lq * 16,
                       reinterpret_cast<const char*>(g_h) + ((size_t)(m * 128 + r) * 256 + lq * 16));
        }
        cp_async_commit_wait();
        __syncthreads();

        float acc[2][8][4];
#pragma unroll
        for (int mb = 0; mb < 2; mb++)
#pragma unroll
            for (int nb = 0; nb < 8; nb++)
#pragma unroll
                for (int j = 0; j < 4; j++) acc[mb][nb][j] = 0.f;

#pragma unroll
        for (int kc = 0; kc < 8; kc++) {
            const uint32_t koff = kc * 32;   // 16 k * 2 bytes
            uint32_t a0[4], a1[4];
            ldsm4(a0, baseA[0] + koff);
            ldsm4(a1, baseA[1] + koff);
#pragma unroll
            for (int nbp = 0; nbp < 4; nbp++) {
                uint32_t bb[4];
                ldsm4(bb, baseB[nbp] + koff);
                mma16816(acc[0][2 * nbp + 0], a0, &bb[0]);
                mma16816(acc[1][2 * nbp + 0], a1, &bb[0]);
                mma16816(acc[0][2 * nbp + 1], a0, &bb[2]);
                mma16816(acc[1][2 * nbp + 1], a1, &bb[2]);
            }
        }

        __syncthreads();   // all A-frag reads done -> epi region writable

        // lean epilogue: pack raw logits to half2 in padded smem
#pragma unroll
        for (int mb = 0; mb < 2; mb++) {
#pragma unroll
            for (int p = 0; p < 2; p++) {
                const int rloc = m_base + mb * 16 + p * 8 + r4;
#pragma unroll
                for (int nb = 0; nb < 8; nb++) {
                    int col = warp_n * 64 + nb * 8 + kq;
                    epi2[rloc * 68 + (col >> 1)] =
                        __floats2half2_rn(acc[mb][nb][p * 2 + 0], acc[mb][nb][p * 2 + 1]);
                }
            }
        }
        __syncthreads();

        // coalesced fp16 store: 128 rows x 128 halves (256B/row)
        for (int i = tid; i < 2048; i += 256) {
            int r = i >> 4, q = i & 15;
            if (q * 8 + 8 <= ncols) {
                uint4 v = *reinterpret_cast<const uint4*>(smem + OFF_A + r * ASTRIDE + q * 16);
                __stcs(reinterpret_cast<uint4*>(
                           g_scrl + (size_t)(m * 128 + r) * VOCAB + jbase + q * 8), v);
            }
        }
    }
}

// ---------------- rowsum: stream logits, exp-sum -> atomicAdd ----------------
// grid (7, BATCH); CTA handles 1792 uint4 (=14336 halves) of one row.
__global__ void __launch_bounds__(256) rowsum_kernel(const float* __restrict__ fc_b) {
    __shared__ float wsum[8];
    const int row = blockIdx.y;
    const int t = threadIdx.x;
    const uint4* src = reinterpret_cast<const uint4*>(g_scrl + (size_t)row * VOCAB);
    float s = 0.f;
#pragma unroll
    for (int k = 0; k < 7; k++) {
        int idx = blockIdx.x * 1792 + k * 256 + t;
        if (idx < VOCAB / 8) {
            uint4 v = __ldcs(src + idx);
            int col = idx * 8;
            float4 b0 = *reinterpret_cast<const float4*>(fc_b + col);
            float4 b1 = *reinterpret_cast<const float4*>(fc_b + col + 4);
            __half2 h;
            h = *reinterpret_cast<__half2*>(&v.x);
            s += __expf(__low2float(h) + b0.x) + __expf(__high2float(h) + b0.y);
            h = *reinterpret_cast<__half2*>(&v.y);
            s += __expf(__low2float(h) + b0.z) + __expf(__high2float(h) + b0.w);
            h = *reinterpret_cast<__half2*>(&v.z);
            s += __expf(__low2float(h) + b1.x) + __expf(__high2float(h) + b1.y);
            h = *reinterpret_cast<__half2*>(&v.w);
            s += __expf(__low2float(h) + b1.z) + __expf(__high2float(h) + b1.w);
        }
    }
#pragma unroll
    for (int o = 16; o; o >>= 1) s += __shfl_xor_sync(0xffffffffu, s, o);
    if ((t & 31) == 0) wsum[t >> 5] = s;
    __syncthreads();
    if (t == 0) {
        float tot = 0.f;
#pragma unroll
        for (int w = 0; w < 8; w++) tot += wsum[w];
        atomicAdd(&g_rowsum[row], tot);
    }
}

// ---------------- scale: out = exp(logit+bias) / rowsum ---------------------
__global__ void __launch_bounds__(256) scale_kernel(const float* __restrict__ fc_b,
                                                    float* __restrict__ out) {
    const uint32_t nq_row = VOCAB / 8;                 // 12500
    uint32_t t = blockIdx.x * 256 + threadIdx.x;
    if (t >= (uint32_t)BATCH * nq_row) return;
    uint32_t row = t / nq_row;
    uint32_t cq = t - row * nq_row;
    float invs = 1.0f / g_rowsum[row];
    int col = cq * 8;
    float4 b0 = *reinterpret_cast<const float4*>(fc_b + col);
    float4 b1 = *reinterpret_cast<const float4*>(fc_b + col + 4);
    uint4 v = __ldcs(reinterpret_cast<const uint4*>(g_scrl + (size_t)row * VOCAB) + cq);
    float4 o0, o1;
    __half2 h;
    h = *reinterpret_cast<__half2*>(&v.x);
    o0.x = __expf(__low2float(h) + b0.x) * invs;  o0.y = __expf(__high2float(h) + b0.y) * invs;
    h = *reinterpret_cast<__half2*>(&v.y);
    o0.z = __expf(__low2float(h) + b0.z) * invs;  o0.w = __expf(__high2float(h) + b0.w) * invs;
    h = *reinterpret_cast<__half2*>(&v.z);
    o1.x = __expf(__low2float(h) + b1.x) * invs;  o1.y = __expf(__high2float(h) + b1.y) * invs;
    h = *reinterpret_cast<__half2*>(&v.w);
    o1.z = __expf(__low2float(h) + b1.z) * invs;  o1.w = __expf(__high2float(h) + b1.w) * invs;
    float4* dst = reinterpret_cast<float4*>(out + (size_t)row * VOCAB) + cq * 2;
    __stcs(dst, o0);
    __stcs(dst + 1, o1);
}

// ---------------- launch ----------------------------------------------------
extern "C" void kernel_launch(void* const* d_in, const int* in_sizes, int n_in,
                              void* d_out, int out_size) {
    const int*   x      = (const int*)d_in[0];
    const float* noise  = (const float*)d_in[1];
    const float* emb    = (const float*)d_in[2];
    const float* W_ih   = (const float*)d_in[3];
    // d_in[4] = W_hh unused (h0 == 0)
    const float* b_ih   = (const float*)d_in[5];
    const float* b_hh   = (const float*)d_in[6];
    const float* fc_w   = (const float*)d_in[7];
    const float* fc_b   = (const float*)d_in[8];
    float* out = (float*)d_out;

    cudaFuncSetAttribute(gemm_pass, cudaFuncAttributeMaxDynamicSharedMemorySize, GEMM_SMEM);

    int n4 = VOCAB * HIDDEN / 4;
    convert_fcw_kernel<<<(n4 + 255) / 256, 256>>>(fc_w);
    prep_kernel<<<1, 512>>>(W_ih, b_ih, b_hh);
    lstm_kernel<<<BATCH / 8, 128>>>(x, noise, emb);

    int ntiles = (VOCAB + 127) / 128;  // 782
    gemm_pass<<<ntiles, 256, GEMM_SMEM>>>();

    rowsum_kernel<<<dim3(7, BATCH), 256>>>(fc_b);

    uint32_t nthr = (uint32_t)BATCH * (VOCAB / 8);   // 25.6M
    scale_kernel<<<(nthr + 255) / 256, 256>>>(fc_b, out);
}